// round 12
// baseline (speedup 1.0000x reference)
#include <cuda_runtime.h>
#include <math.h>

#define NB 32
#define NS 2048
#define NH 768
#define NO 768
#define NK 64
#define GRID 148
#define TPB 512
#define NAT 128                 // attention blocks: 4 per batch, 1 token/warp
#define NGRP 2                  // batch groups of 16
#define NOT 24                  // o-tiles (32 cols)
#define NHS 6                   // h-splits
#define HCHUNK 128
#define NTASK (NGRP * NOT * NHS)   // 288 GEMM tasks

// scratch (plain stores, fully overwritten per launch => replay-safe)
__device__ float g_pp[NAT * NH];        // per-block partial unnormalized pooled
__device__ float g_zp[NAT];             // per-block partial Z
__device__ float g_e[NB * NK];          // unnormalized attention weights
__device__ float g_part[NGRP * NHS * 16 * NO]; // GEMM partials [g*6+hs][16b][o]
__device__ unsigned long long g_epoch;  // launch-epoch derivation
__device__ unsigned long long g_grp[NGRP];   // attention completions per group (64/launch)
__device__ unsigned long long g_fin[NOT];    // per-otile GEMM completions (12/launch)
__device__ float g_sink;

__global__ void __launch_bounds__(TPB)
fused_kernel(const float* __restrict__ hidden,        // (B,S,H)
             const int*   __restrict__ token_idxs,    // (B,K) sorted
             const float* __restrict__ subject_hidden,// unused (softmax shift-invariant)
             const float* __restrict__ Wa,            // (2H,1): only Wa[H:2H] used
             const float* __restrict__ ba,            // unused (shift-invariant)
             const float* __restrict__ Wo,            // (H,O)
             const float* __restrict__ bo,            // (O,)
             float*       __restrict__ out_t,         // (B,O)
             float*       __restrict__ out_aw)        // (B,S)
{
    const int tid  = threadIdx.x;
    const int warp = tid >> 5;
    const int lane = tid & 31;
    const int blk  = blockIdx.x;

    __shared__ __align__(16) float s_part[8][NH];       // 24 KB attention staging
    __shared__ __align__(16) float s_pd[16 * HCHUNK];   // 8 KB GEMM staging
    __shared__ float s_e[16];
    __shared__ float s_invz[NB];
    __shared__ unsigned long long s_epoch;
    __shared__ int s_last;

    // ---- epoch: one atomic per block; all blocks of a launch get the same value ----
    if (tid == 0) {
        unsigned long long t = atomicAdd(&g_epoch, 1ULL);
        s_epoch = t / GRID + 1ULL;
    }
    __syncthreads();
    const unsigned long long epoch = s_epoch;

    // ===== producers: attention (blk<128) | zero+prefetch+scatter (128..147) =====
    if (blk < NAT) {
        const int b   = blk >> 2;
        const int sub = blk & 3;
        const int j   = sub * 16 + warp;

        const int ix = token_idxs[b * NK + j];
        const bool valid = (j == 0) || (ix != token_idxs[b * NK + j - 1]);

        const float4* row = (const float4*)(hidden + ((size_t)b * NS + ix) * NH);
        const float4* wv  = (const float4*)(Wa + NH);
        float4 rv[6], wr[6];
        #pragma unroll
        for (int i = 0; i < 6; i++) { rv[i] = row[i * 32 + lane]; wr[i] = wv[i * 32 + lane]; }

        float p = 0.f;
        #pragma unroll
        for (int i = 0; i < 6; i++) {
            p = fmaf(rv[i].x, wr[i].x, p); p = fmaf(rv[i].y, wr[i].y, p);
            p = fmaf(rv[i].z, wr[i].z, p); p = fmaf(rv[i].w, wr[i].w, p);
        }
        #pragma unroll
        for (int o = 16; o; o >>= 1) p += __shfl_xor_sync(0xffffffffu, p, o);
        const float e = valid ? __expf(p) : 0.f;        // |p| ~ 0.55: no max-sub needed
        if (lane == 0) { s_e[warp] = e; g_e[b * NK + j] = e; }

        // block-reduce 16 warps' e*row in two 8-warp rounds
        if (warp < 8) {
            #pragma unroll
            for (int i = 0; i < 6; i++) {
                float4 v = make_float4(e * rv[i].x, e * rv[i].y, e * rv[i].z, e * rv[i].w);
                *(float4*)&s_part[warp][i * 128 + lane * 4] = v;
            }
        }
        __syncthreads();
        float ps0 = 0.f, ps1 = 0.f;
        #pragma unroll
        for (int k = 0; k < 8; k++) ps0 += s_part[k][tid];
        if (tid < 256) {
            #pragma unroll
            for (int k = 0; k < 8; k++) ps1 += s_part[k][512 + tid];
        }
        __syncthreads();
        if (warp >= 8) {
            #pragma unroll
            for (int i = 0; i < 6; i++) {
                float4 v = make_float4(e * rv[i].x, e * rv[i].y, e * rv[i].z, e * rv[i].w);
                *(float4*)&s_part[warp - 8][i * 128 + lane * 4] = v;
            }
        }
        __syncthreads();
        #pragma unroll
        for (int k = 0; k < 8; k++) ps0 += s_part[k][tid];
        if (tid < 256) {
            #pragma unroll
            for (int k = 0; k < 8; k++) ps1 += s_part[k][512 + tid];
        }
        g_pp[blk * NH + tid] = ps0;
        if (tid < 256) g_pp[blk * NH + 512 + tid] = ps1;
        if (tid == 0) {
            float z = 0.f;
            #pragma unroll
            for (int w = 0; w < 16; w++) z += s_e[w];
            g_zp[blk] = z;
        }
        // signal: this group gained one completed attention block
        __threadfence();
        __syncthreads();
        if (tid == 0) atomicAdd(&g_grp[blk >> 6], 1ULL);
    } else if (blk < NAT + 16) {
        // scatter block i: batches 2i, 2i+1. Zero own rows, help prefetch, wait, scatter.
        const int i  = blk - NAT;
        const int b0 = 2 * i;
        const int g  = i >> 3;
        #pragma unroll
        for (int r = 0; r < 2; r++)
            ((float4*)(out_aw + (size_t)(b0 + r) * NS))[tid] = make_float4(0.f, 0.f, 0.f, 0.f);

        // help prefetch Wo into L2 (20 blocks total share it)
        {
            const float4* w4 = (const float4*)Wo;
            float acc = 0.f;
            for (int q = (blk - NAT) * TPB + tid; q < (NH * NO) / 4; q += 20 * TPB) {
                float4 w = w4[q];
                acc += w.x + w.y + w.z + w.w;
            }
            if (acc == 123456789.0f) g_sink = acc;
        }
        // wait for this group's 64 attention blocks
        if (tid == 0) {
            volatile unsigned long long* p = &g_grp[g];
            while (*p < epoch * 64ULL) __nanosleep(20);
            __threadfence();
        }
        __syncthreads();
        if (tid < 128) {
            const int b = b0 + (tid >> 6);
            const int j = tid & 63;
            float e = g_e[b * NK + j];
            if (e != 0.f) {
                const float* zp = g_zp + b * 4;
                float iz = 1.0f / (zp[0] + zp[1] + zp[2] + zp[3]);
                out_aw[(size_t)b * NS + token_idxs[b * NK + j]] = e * iz;
            }
        }
    } else {
        // blocks 144-147: help prefetch Wo
        const float4* w4 = (const float4*)Wo;
        float acc = 0.f;
        for (int q = (blk - NAT) * TPB + tid; q < (NH * NO) / 4; q += 20 * TPB) {
            float4 w = w4[q];
            acc += w.x + w.y + w.z + w.w;
        }
        if (acc == 123456789.0f) g_sink = acc;
    }

    // ===== consumers: static GEMM tasks, gated per-group (no global barrier) =====
    for (int t = blk; t < NTASK; t += GRID) {
        const int g     = t / (NOT * NHS);
        const int rem   = t % (NOT * NHS);
        const int otile = rem % NOT;
        const int hs    = rem / NOT;
        const int h0    = hs * HCHUNK;

        // wait: group g's 64 attention blocks done (producers never wait on us)
        __syncthreads();
        if (tid == 0) {
            volatile unsigned long long* p = &g_grp[g];
            while (*p < epoch * 64ULL) __nanosleep(20);
            __threadfence();
        }
        __syncthreads();

        // stage Σ of 4 per-block pooled partials for this group's 16 batches
        for (int q = tid; q < 16 * HCHUNK; q += TPB) {
            int bb = q >> 7, hh = q & 127;
            const float* pp = g_pp + (size_t)((g * 16 + bb) * 4) * NH + h0 + hh;
            s_pd[q] = pp[0] + pp[NH] + pp[2 * NH] + pp[3 * NH];
        }
        __syncthreads();

        const int ol = tid & 31;
        const int bb = tid >> 5;                       // 0..15 (warp-uniform)
        const int o  = otile * 32 + ol;
        const float* w  = Wo + (size_t)h0 * NO + o;
        const float* pd = s_pd + bb * HCHUNK;
        float acc = 0.f;
        #pragma unroll 8
        for (int hh = 0; hh < HCHUNK; hh++)
            acc = fmaf(pd[hh], w[(size_t)hh * NO], acc);   // LDS bcast + L1-shared line
        g_part[(size_t)(g * NHS + hs) * 16 * NO + bb * NO + o] = acc;

        __threadfence();
        __syncthreads();
        if (tid == 0) {
            unsigned long long tt = atomicAdd(&g_fin[otile], 1ULL);
            s_last = (tt == epoch * (NGRP * NHS) - 1ULL);  // 12 tasks per otile per launch
        }
        __syncthreads();

        if (s_last) {                                  // finalize otile: 32 o x 32 b
            __threadfence();
            if (tid < NB) {
                const float* zp = g_zp + tid * 4;
                s_invz[tid] = 1.0f / (zp[0] + zp[1] + zp[2] + zp[3]);
            }
            __syncthreads();
            const int fo = otile * 32 + (tid & 31);
            #pragma unroll
            for (int r = 0; r < 2; r++) {
                const int fb = (tid >> 5) + r * 16;
                const int fg = fb >> 4, lb = fb & 15;
                float sum = 0.f;
                #pragma unroll
                for (int h2 = 0; h2 < NHS; h2++)
                    sum += g_part[(size_t)(fg * NHS + h2) * 16 * NO + lb * NO + fo];
                out_t[(size_t)fb * NO + fo] = tanhf(fmaf(sum, s_invz[fb], bo[fo]));
            }
            __syncthreads();
        }
    }
}

// ---------------------------------------------------------------------------
extern "C" void kernel_launch(void* const* d_in, const int* in_sizes, int n_in,
                              void* d_out, int out_size)
{
    const float* hidden         = (const float*)d_in[0];
    const int*   token_idxs     = (const int*)  d_in[1];
    const float* subject_hidden = (const float*)d_in[2];
    const float* Wa             = (const float*)d_in[3];
    const float* ba             = (const float*)d_in[4];
    const float* Wo             = (const float*)d_in[5];
    const float* bo             = (const float*)d_in[6];

    float* out_transformed = (float*)d_out;              // (B,O)
    float* out_aw          = (float*)d_out + NB * NO;    // (B,S)

    fused_kernel<<<GRID, TPB>>>(hidden, token_idxs, subject_hidden,
                                Wa, ba, Wo, bo, out_transformed, out_aw);
}

// round 13
// speedup vs baseline: 1.3611x; 1.3611x over previous
#include <cuda_runtime.h>
#include <math.h>

#define NB 32
#define NS 2048
#define NH 768
#define NO 768
#define NK 64
#define GRID 148
#define TPB 512
#define NAT 128                 // attention blocks: 4 per batch, 1 token/warp
#define NOT 24                  // o-tiles (32 cols)
#define NHS 6                   // h-splits
#define HCHUNK 128

// inter-phase scratch (plain stores only: fully overwritten every launch, replay-safe)
__device__ float g_pp[NAT * NH];        // per-block partial unnormalized pooled
__device__ float g_zp[NAT];             // per-block partial Z
__device__ float g_e[NB * NK];          // unnormalized attention weights
__device__ float g_invZ[NB];
__device__ float g_part[NHS * NB * NO]; // GEMM partials
__device__ unsigned long long g_bar[2]; // monotonic barrier counters
__device__ float g_sink;

__device__ __forceinline__ void grid_barrier(int i)
{
    __syncthreads();
    if (threadIdx.x == 0) {
        __threadfence();
        unsigned long long t = atomicAdd(&g_bar[i], 1ULL);
        unsigned long long target = (t / GRID + 1ULL) * GRID;
        volatile unsigned long long* p = &g_bar[i];
        while (*p < target) __nanosleep(20);
        __threadfence();
    }
    __syncthreads();
}

__global__ void __launch_bounds__(TPB)
fused_kernel(const float* __restrict__ hidden,        // (B,S,H)
             const int*   __restrict__ token_idxs,    // (B,K) sorted
             const float* __restrict__ subject_hidden,// unused (softmax shift-invariant)
             const float* __restrict__ Wa,            // (2H,1): only Wa[H:2H] used
             const float* __restrict__ ba,            // unused (shift-invariant)
             const float* __restrict__ Wo,            // (H,O)
             const float* __restrict__ bo,            // (O,)
             float*       __restrict__ out_t,         // (B,O)
             float*       __restrict__ out_aw)        // (B,S)
{
    const int tid  = threadIdx.x;
    const int warp = tid >> 5;
    const int lane = tid & 31;
    const int blk  = blockIdx.x;

    __shared__ __align__(16) float s_part[8][NH];      // 24 KB staging
    __shared__ __align__(16) float s_pd[32 * HCHUNK];  // 16 KB GEMM staging
    __shared__ float s_e[16];
    __shared__ float s_invz[NB];

    // ===== PHASE A: attention, 1 token/warp (blk<128) | zero aw + prefetch Wo =====
    if (blk < NAT) {
        const int b   = blk >> 2;
        const int sub = blk & 3;
        const int j   = sub * 16 + warp;

        const int ix = token_idxs[b * NK + j];
        const bool valid = (j == 0) || (ix != token_idxs[b * NK + j - 1]);

        // load row + Wa[H:2H] slice (24 independent float4 each: full MLP)
        const float4* row = (const float4*)(hidden + ((size_t)b * NS + ix) * NH);
        const float4* wv  = (const float4*)(Wa + NH);
        float4 rv[6], wr[6];
        #pragma unroll
        for (int i = 0; i < 6; i++) { rv[i] = row[i * 32 + lane]; wr[i] = wv[i * 32 + lane]; }

        // dot with 4 independent accumulator chains (breaks 96-FMA serial chain)
        float p0 = 0.f, p1 = 0.f, p2 = 0.f, p3 = 0.f;
        #pragma unroll
        for (int i = 0; i < 6; i++) {
            p0 = fmaf(rv[i].x, wr[i].x, p0);
            p1 = fmaf(rv[i].y, wr[i].y, p1);
            p2 = fmaf(rv[i].z, wr[i].z, p2);
            p3 = fmaf(rv[i].w, wr[i].w, p3);
        }
        float p = (p0 + p1) + (p2 + p3);
        #pragma unroll
        for (int o = 16; o; o >>= 1) p += __shfl_xor_sync(0xffffffffu, p, o);
        const float e = valid ? __expf(p) : 0.f;       // |p| ~ 0.55: no max-sub needed
        if (lane == 0) { s_e[warp] = e; g_e[b * NK + j] = e; }

        // block-reduce 16 warps' e*row in two 8-warp rounds
        if (warp < 8) {
            #pragma unroll
            for (int i = 0; i < 6; i++) {
                float4 v = make_float4(e * rv[i].x, e * rv[i].y, e * rv[i].z, e * rv[i].w);
                *(float4*)&s_part[warp][i * 128 + lane * 4] = v;
            }
        }
        __syncthreads();
        float ps0 = 0.f, ps1 = 0.f;
        {   // two independent 4-term chains per column
            float a = 0.f, c = 0.f;
            #pragma unroll
            for (int k = 0; k < 8; k += 2) { a += s_part[k][tid]; c += s_part[k + 1][tid]; }
            ps0 = a + c;
        }
        if (tid < 256) {
            float a = 0.f, c = 0.f;
            #pragma unroll
            for (int k = 0; k < 8; k += 2) { a += s_part[k][512 + tid]; c += s_part[k + 1][512 + tid]; }
            ps1 = a + c;
        }
        __syncthreads();
        if (warp >= 8) {
            #pragma unroll
            for (int i = 0; i < 6; i++) {
                float4 v = make_float4(e * rv[i].x, e * rv[i].y, e * rv[i].z, e * rv[i].w);
                *(float4*)&s_part[warp - 8][i * 128 + lane * 4] = v;
            }
        }
        __syncthreads();
        {
            float a = 0.f, c = 0.f;
            #pragma unroll
            for (int k = 0; k < 8; k += 2) { a += s_part[k][tid]; c += s_part[k + 1][tid]; }
            ps0 += a + c;
        }
        if (tid < 256) {
            float a = 0.f, c = 0.f;
            #pragma unroll
            for (int k = 0; k < 8; k += 2) { a += s_part[k][512 + tid]; c += s_part[k + 1][512 + tid]; }
            ps1 += a + c;
        }
        g_pp[blk * NH + tid] = ps0;
        if (tid < 256) g_pp[blk * NH + 512 + tid] = ps1;
        if (tid == 0) {
            float z = 0.f;
            #pragma unroll
            for (int w = 0; w < 16; w++) z += s_e[w];
            g_zp[blk] = z;
        }
    } else {
        // 20 blocks: zero aw (256 KB) then prefetch Wo (2.36 MB) into L2
        const int nth = (GRID - NAT) * TPB;
        const int g0  = (blk - NAT) * TPB + tid;
        float4 z4 = make_float4(0.f, 0.f, 0.f, 0.f);
        for (int i = g0; i < (NB * NS) / 4; i += nth)
            ((float4*)out_aw)[i] = z4;
        const float4* w4 = (const float4*)Wo;
        float acc = 0.f;
        for (int i = g0; i < (NH * NO) / 4; i += nth) {
            float4 w = __ldg(&w4[i]);
            acc += w.x + w.y + w.z + w.w;
        }
        if (acc == 123456789.0f) g_sink = acc;         // never true; defeats DCE
    }
    grid_barrier(0);

    // ===== PHASE B: GEMM partials (144 blocks) + invZ/scatter (block 144) =====
    if (blk < NOT * NHS) {
        const int otile = blk % NOT;
        const int hs    = blk / NOT;
        const int h0    = hs * HCHUNK;

        // stage Σ of 4 per-block partial pooled vectors (unnormalized)
        for (int i = tid; i < 32 * HCHUNK; i += TPB) {
            int bb = i >> 7, hh = i & 127;
            const float* pp = g_pp + (size_t)(bb * 4) * NH + h0 + hh;
            s_pd[i] = (pp[0] + pp[NH]) + (pp[2 * NH] + pp[3 * NH]);
        }
        __syncthreads();

        const int ol = tid & 31;
        const int bb = tid >> 5;                       // 0..15 (warp-uniform)
        const int o  = otile * 32 + ol;
        const float* w  = Wo + (size_t)h0 * NO + o;
        const float* p0 = s_pd + bb * HCHUNK;
        const float* p1 = s_pd + (bb + 16) * HCHUNK;
        // 2 accumulators per output (even/odd hh): halves the dependent chain
        float a0e = 0.f, a0o = 0.f, a1e = 0.f, a1o = 0.f;
        #pragma unroll 8
        for (int hh = 0; hh < HCHUNK; hh += 2) {
            float w0 = __ldg(&w[(size_t)hh * NO]);
            float w1 = __ldg(&w[(size_t)(hh + 1) * NO]);
            a0e = fmaf(p0[hh],     w0, a0e);
            a0o = fmaf(p0[hh + 1], w1, a0o);
            a1e = fmaf(p1[hh],     w0, a1e);
            a1o = fmaf(p1[hh + 1], w1, a1o);
        }
        g_part[(size_t)hs * NB * NO + bb * NO + o]        = a0e + a0o;
        g_part[(size_t)hs * NB * NO + (bb + 16) * NO + o] = a1e + a1o;
    } else if (blk == NOT * NHS) {
        // invZ + scatter attention weights
        if (tid < NB) {
            const float* zp = g_zp + tid * 4;
            float iz = 1.0f / ((zp[0] + zp[1]) + (zp[2] + zp[3]));
            s_invz[tid] = iz;
            g_invZ[tid] = iz;
        }
        __syncthreads();
        #pragma unroll
        for (int r = 0; r < 4; r++) {
            int item = r * TPB + tid;                  // 2048 = 32b x 64j
            int b = item >> 6;
            float e = g_e[item];
            if (e != 0.f)
                out_aw[(size_t)b * NS + token_idxs[item]] = e * s_invz[b];
        }
    }
    grid_barrier(1);

    // ===== PHASE C: reduce partials, normalize, bias, tanh (48 blocks) =====
    if (blk < (NB * NO) / TPB) {
        const int gid = blk * TPB + tid;
        const int b   = gid / NO;
        const int o   = gid - b * NO;
        float s0 = 0.f, s1 = 0.f;
        #pragma unroll
        for (int hs = 0; hs < NHS; hs += 2) {
            s0 += g_part[(size_t)hs * NB * NO + gid];
            s1 += g_part[(size_t)(hs + 1) * NB * NO + gid];
        }
        out_t[gid] = tanhf(fmaf(s0 + s1, g_invZ[b], bo[o]));
    }
}

// ---------------------------------------------------------------------------
extern "C" void kernel_launch(void* const* d_in, const int* in_sizes, int n_in,
                              void* d_out, int out_size)
{
    const float* hidden         = (const float*)d_in[0];
    const int*   token_idxs     = (const int*)  d_in[1];
    const float* subject_hidden = (const float*)d_in[2];
    const float* Wa             = (const float*)d_in[3];
    const float* ba             = (const float*)d_in[4];
    const float* Wo             = (const float*)d_in[5];
    const float* bo             = (const float*)d_in[6];

    float* out_transformed = (float*)d_out;              // (B,O)
    float* out_aw          = (float*)d_out + NB * NO;    // (B,S)

    fused_kernel<<<GRID, TPB>>>(hidden, token_idxs, subject_hidden,
                                Wa, ba, Wo, bo, out_transformed, out_aw);
}